// round 1
// baseline (speedup 1.0000x reference)
#include <cuda_runtime.h>
#include <math.h>

#define POOL 7
#define ROI_SCALE 0.0625f

// One thread per output bin: out[n][c][ph][pw].
// Replicates the reference's crop->pad->maxpool semantics exactly:
//   len   = max(q-p+1, 1)
//   psize = ceil(len/POOL)
//   pad0  = (psize*POOL - len) / 2
//   bin j covers logical padded cells [j*psize, (j+1)*psize), mapped to
//   feature coords i = p - pad0 + cell.  Cells outside [p,q] are zero-pad:
//   has_pad bins compete their max with 0; fully-padded bins are 0.
__global__ void roipool_kernel(const float* __restrict__ feat,
                               const float* __restrict__ rois,
                               float* __restrict__ out,
                               int N, int C, int H, int W) {
    int idx = blockIdx.x * blockDim.x + threadIdx.x;
    int total = N * C * POOL * POOL;
    if (idx >= total) return;

    int pw = idx % POOL;
    int ph = (idx / POOL) % POOL;
    int c  = (idx / (POOL * POOL)) % C;
    int n  = idx / (POOL * POOL * C);

    const float* r = rois + n * 5;
    int b  = (int)r[0];
    // jnp.round = round-half-to-even = __float2int_rn
    int px = __float2int_rn(r[1] * ROI_SCALE);
    int py = __float2int_rn(r[2] * ROI_SCALE);
    int qx = __float2int_rn(r[3] * ROI_SCALE);
    int qy = __float2int_rn(r[4] * ROI_SCALE);

    int lenx = max(qx - px + 1, 1);
    int leny = max(qy - py + 1, 1);
    int psx  = (lenx + POOL - 1) / POOL;
    int psy  = (leny + POOL - 1) / POOL;
    int pad0x = (psx * POOL - lenx) / 2;
    int pad0y = (psy * POOL - leny) / 2;

    // feature-coord range for this bin, clipped to the ROI rectangle
    int xs = px - pad0x + pw * psx;
    int xe = xs + psx - 1;
    int ys = py - pad0y + ph * psy;
    int ye = ys + psy - 1;

    bool padx = (pw * psx < pad0x) | ((pw + 1) * psx > pad0x + lenx);
    bool pady = (ph * psy < pad0y) | ((ph + 1) * psy > pad0y + leny);

    int cxs = max(xs, px), cxe = min(xe, qx);
    int cys = max(ys, py), cye = min(ye, qy);

    float m;
    if (cxs > cxe || cys > cye) {
        // bin entirely in zero-pad region
        m = 0.0f;
    } else {
        m = -INFINITY;
        const float* fc = feat + ((size_t)b * C + c) * H * W;
        for (int y = cys; y <= cye; ++y) {
            const float* row = fc + y * W;
            #pragma unroll 4
            for (int x = cxs; x <= cxe; ++x) {
                m = fmaxf(m, __ldg(row + x));
            }
        }
        if (padx | pady) m = fmaxf(m, 0.0f);
    }
    out[idx] = m;
}

// Second output of the reference tuple: batch ids, as floats.
__global__ void bid_kernel(const float* __restrict__ rois,
                           float* __restrict__ out, int N) {
    int n = blockIdx.x * blockDim.x + threadIdx.x;
    if (n < N) out[n] = (float)((int)rois[n * 5]);
}

extern "C" void kernel_launch(void* const* d_in, const int* in_sizes, int n_in,
                              void* d_out, int out_size) {
    const float* feat = (const float*)d_in[0];
    const float* rois = (const float*)d_in[1];
    float* out = (float*)d_out;

    const int C = 256, H = 64, W = 64;
    int N = in_sizes[1] / 5;
    int B = in_sizes[0] / (C * H * W);
    (void)B;

    int total = N * C * POOL * POOL;
    int threads = 256;
    int blocks = (total + threads - 1) / threads;
    roipool_kernel<<<blocks, threads>>>(feat, rois, out, N, C, H, W);

    // If the harness concatenates the (out, bid) tuple, fill the tail too.
    if (out_size >= total + N) {
        bid_kernel<<<1, 256>>>(rois, out + total, N);
    }
}